// round 16
// baseline (speedup 1.0000x reference)
#include <cuda_runtime.h>
#include <cuda_fp16.h>
#include <cstdint>

// VectorQuantizer via mma.sync (HMMA) fp16 3-product split-GEMM.
// Warp owns 32 pixel rows (2 m16 tiles) sharing one B load.
// Interleaved two-tile MMA issue with deferred folds (2 chains/tile).
// z [16,64,64,64] f32, embed [1024,64] f32.
// out[0..4194303] = z_q_st, out[4194304] = loss.

#define CDIM   64
#define NPX    65536
#define OUT_Q  4194304
#define KTOT   1024
#define TPB    256
#define MPX    256         // pixels per CTA
#define CHK    32          // codes per chunk (double-buffered)
#define NCHUNK 32
#define NGRP   4           // 8-code groups per chunk
#define ROWB   144         // padded row bytes -> conflict-free ldmatrix

// ---- smem byte offsets ----
#define SM_ZH   0                         // [256 px][72 halves] 36864
#define SM_ZL   36864
#define SM_EB   73728                     // 2 bufs x {EH 4608, EL 4608} = 18432
#define SM_EE   92160                     // [1024] f32
#define SM_ZZ   96256                     // [256] f32
#define SM_IDX  97280                     // [256] int
#define SM_RED  98304                     // [8] f32 (warp partials)
#define SM_TOT  99328
#define EBUF(b) (SM_EB + (b) * 9216)

__device__ uint4 g_ebh[KTOT * 8];   // fp16(1024*e)  [1024][64] halves
__device__ uint4 g_ebl[KTOT * 8];   // fp16 residual
__device__ float g_ee[KTOT];

__device__ __forceinline__ uint32_t smem_u32(const void* p) {
    uint32_t a;
    asm("{ .reg .u64 t; cvta.to.shared.u64 t, %1; cvt.u32.u64 %0, t; }"
        : "=r"(a) : "l"(p));
    return a;
}
__device__ __forceinline__ void ldsm4(uint32_t& r0, uint32_t& r1, uint32_t& r2,
                                      uint32_t& r3, uint32_t addr) {
    asm volatile("ldmatrix.sync.aligned.m8n8.x4.shared.b16 {%0,%1,%2,%3}, [%4];"
                 : "=r"(r0), "=r"(r1), "=r"(r2), "=r"(r3) : "r"(addr));
}
__device__ __forceinline__ void mma16816(float& d0, float& d1, float& d2, float& d3,
                                         uint32_t a0, uint32_t a1, uint32_t a2,
                                         uint32_t a3, uint32_t b0, uint32_t b1) {
    asm volatile(
        "mma.sync.aligned.m16n8k16.row.col.f32.f16.f16.f32 "
        "{%0,%1,%2,%3}, {%4,%5,%6,%7}, {%8,%9}, {%0,%1,%2,%3};"
        : "+f"(d0), "+f"(d1), "+f"(d2), "+f"(d3)
        : "r"(a0), "r"(a1), "r"(a2), "r"(a3), "r"(b0), "r"(b1));
}
__device__ __forceinline__ void amerge(float& d, int& i, float d2, int i2) {
    if (d2 < d || (d2 == d && i2 < i)) { d = d2; i = i2; }
}
#define CPA16(s, g) \
    asm volatile("cp.async.cg.shared.global [%0], [%1], 16;" \
                 :: "r"(s), "l"(g) : "memory")
#define CPA_COMMIT() asm volatile("cp.async.commit_group;" ::: "memory")
#define CPA_WAIT0()  asm volatile("cp.async.wait_group 0;" ::: "memory")

// ---------------- precompute: split codebook, ee (warp per code) ----------------
__global__ void vq_pre(const float* __restrict__ embed, float* out, int out_size) {
    const int gid  = blockIdx.x * blockDim.x + threadIdx.x;
    const int k    = gid >> 5;            // warp id = code
    const int lane = threadIdx.x & 31;
    if (gid == 0 && out_size > OUT_Q) out[OUT_Q] = 0.0f;
    if (k >= KTOT) return;

    float2 v = *(const float2*)(embed + k * CDIM + lane * 2);   // coalesced
    float s = v.x * v.x + v.y * v.y;
#pragma unroll
    for (int x = 16; x > 0; x >>= 1)
        s += __shfl_xor_sync(0xffffffff, s, x);                 // ee (order-free)

    float w0 = v.x * 1024.0f, w1 = v.y * 1024.0f;               // exact scaling
    __half h0 = __float2half_rn(w0);
    __half h1 = __float2half_rn(w1);
    __half l0 = __float2half_rn(w0 - __half2float(h0));
    __half l1 = __float2half_rn(w1 - __half2float(h1));
    ((__half2*)g_ebh)[k * 32 + lane] = __halves2half2(h0, h1);  // coalesced
    ((__half2*)g_ebl)[k * 32 + lane] = __halves2half2(l0, l1);
    if (lane == 0) g_ee[k] = s;
}

// ---------------- main kernel ----------------
__global__ __launch_bounds__(TPB, 2)
void vq_main(const float* __restrict__ z,
             const float* __restrict__ embed,
             float* __restrict__ out, int out_size)
{
    extern __shared__ unsigned char smem[];
    const uint32_t sb = smem_u32(smem);
    float* ee  = (float*)(smem + SM_EE);
    float* szz = (float*)(smem + SM_ZZ);
    int*   sidx = (int*)(smem + SM_IDX);
    float* red = (float*)(smem + SM_RED);

    const int t    = threadIdx.x;
    const int lane = t & 31;
    const int w    = t >> 5;              // warp 0..7: rows w*32..w*32+31

    const int base = blockIdx.x * MPX;
    const int b    = base >> 12;
    const int po   = base & 4095;
    const float* zb = z + ((size_t)b << 18) + po;

    // ---- stage chunk 0 immediately ----
    {
        uint32_t off = (uint32_t)((t >> 3) * ROWB + (t & 7) * 16);
        CPA16(sb + EBUF(0) + off,        g_ebh + t);
        CPA16(sb + EBUF(0) + 4608 + off, g_ebl + t);
        CPA_COMMIT();
    }

    // ---- ee table ----
#pragma unroll
    for (int j = 0; j < 4; ++j) ee[t + j * 256] = g_ee[t + j * 256];

    // ---- load z column for my pixel (px = t): split + zz in one pass ----
    {
        __half* zhp = (__half*)(smem + SM_ZH) + t * 72;
        __half* zlp = (__half*)(smem + SM_ZL) + t * 72;
        float s = 0.0f;
#pragma unroll
        for (int c = 0; c < CDIM; ++c) {
            float v = zb[(c << 12) + t];
            s = __fadd_rn(s, __fmul_rn(v, v));    // reference rounding, sequential
            __half h = __float2half_rn(v);
            __half l = __float2half_rn(v - __half2float(h));
            zhp[c] = h;
            zlp[c] = l;
        }
        szz[t] = s;
    }
    __syncthreads();

    // ---- A fragments (register resident): 2 tiles x 4 ksteps x {zh, zl} ----
    uint32_t aH[2][4][4], aL[2][4][4];
    {
        const int m    = lane >> 3;
        const int coff = (m >> 1) * 16;
#pragma unroll
        for (int tl = 0; tl < 2; ++tl) {
            const int arow = w * 32 + tl * 16 + (m & 1) * 8 + (lane & 7);
            uint32_t adH = sb + SM_ZH + arow * ROWB + coff;
            uint32_t adL = sb + SM_ZL + arow * ROWB + coff;
#pragma unroll
            for (int ks = 0; ks < 4; ++ks) {
                ldsm4(aH[tl][ks][0], aH[tl][ks][1], aH[tl][ks][2], aH[tl][ks][3],
                      adH + ks * 32);
                ldsm4(aL[tl][ks][0], aL[tl][ks][1], aL[tl][ks][2], aL[tl][ks][3],
                      adL + ks * 32);
            }
        }
    }

    const int rq = lane >> 2;
    const float zzA0 = szz[w * 32 + rq],      zzA8 = szz[w * 32 + 8 + rq];
    const float zzB0 = szz[w * 32 + 16 + rq], zzB8 = szz[w * 32 + 24 + rq];

    float bdA0 = 3.4e38f, bdA1 = 3.4e38f, bdA2 = 3.4e38f, bdA3 = 3.4e38f;
    float bdB0 = 3.4e38f, bdB1 = 3.4e38f, bdB2 = 3.4e38f, bdB3 = 3.4e38f;
    int biA0 = 0, biA1 = 0, biA2 = 0, biA3 = 0;
    int biB0 = 0, biB1 = 0, biB2 = 0, biB3 = 0;

    const uint32_t blane = (lane & 7) * ROWB + (lane >> 3) * 16;
    const int cql = 2 * (lane & 3);

    for (int ch = 0; ch < NCHUNK; ++ch) {
        const int buf = ch & 1;
        CPA_WAIT0();
        __syncthreads();

        // prefetch chunk ch+1 into the other buffer
        if (ch + 1 < NCHUNK) {
            const uint4* srcH = g_ebh + (ch + 1) * CHK * 8;
            const uint4* srcL = g_ebl + (ch + 1) * CHK * 8;
            const uint32_t db = sb + EBUF(buf ^ 1);
            uint32_t off = (uint32_t)((t >> 3) * ROWB + (t & 7) * 16);
            CPA16(db + off,        srcH + t);
            CPA16(db + 4608 + off, srcL + t);
            CPA_COMMIT();
        }

        const uint32_t bH0 = sb + EBUF(buf) + blane;
        const uint32_t bL0 = bH0 + 4608;

#pragma unroll
        for (int g = 0; g < NGRP; ++g) {
            const uint32_t bo = (uint32_t)(g * 8 * ROWB);
            uint32_t bh[8], bl[8];
            ldsm4(bh[0], bh[1], bh[2], bh[3], bH0 + bo);
            ldsm4(bh[4], bh[5], bh[6], bh[7], bH0 + bo + 64);
            ldsm4(bl[0], bl[1], bl[2], bl[3], bL0 + bo);
            ldsm4(bl[4], bl[5], bl[6], bl[7], bL0 + bo + 64);

            const int k0 = ch * CHK + g * 8 + cql;
            const float e0 = ee[k0], e1 = ee[k0 + 1];

            // ---- both tiles interleaved: 24 MMAs, 4 chains (2 per tile) ----
            // p-chain: aH*bh (ks0-3) then aL*bh (ks0-3); q-chain: aH*bl.
            // Summation tree identical to the validated R6 kernel: d = p + q.
            float pA0 = 0.f, pA1 = 0.f, pA2 = 0.f, pA3 = 0.f;
            float qA0 = 0.f, qA1 = 0.f, qA2 = 0.f, qA3 = 0.f;
            float pB0 = 0.f, pB1 = 0.f, pB2 = 0.f, pB3 = 0.f;
            float qB0 = 0.f, qB1 = 0.f, qB2 = 0.f, qB3 = 0.f;
#pragma unroll
            for (int ks = 0; ks < 4; ++ks) {
                mma16816(pA0, pA1, pA2, pA3, aH[0][ks][0], aH[0][ks][1],
                         aH[0][ks][2], aH[0][ks][3], bh[2 * ks], bh[2 * ks + 1]);
                mma16816(pB0, pB1, pB2, pB3, aH[1][ks][0], aH[1][ks][1],
                         aH[1][ks][2], aH[1][ks][3], bh[2 * ks], bh[2 * ks + 1]);
                mma16816(qA0, qA1, qA2, qA3, aH[0][ks][0], aH[0][ks][1],
                         aH[0][ks][2], aH[0][ks][3], bl[2 * ks], bl[2 * ks + 1]);
                mma16816(qB0, qB1, qB2, qB3, aH[1][ks][0], aH[1][ks][1],
                         aH[1][ks][2], aH[1][ks][3], bl[2 * ks], bl[2 * ks + 1]);
            }
#pragma unroll
            for (int ks = 0; ks < 4; ++ks) {
                mma16816(pA0, pA1, pA2, pA3, aL[0][ks][0], aL[0][ks][1],
                         aL[0][ks][2], aL[0][ks][3], bh[2 * ks], bh[2 * ks + 1]);
                mma16816(pB0, pB1, pB2, pB3, aL[1][ks][0], aL[1][ks][1],
                         aL[1][ks][2], aL[1][ks][3], bh[2 * ks], bh[2 * ks + 1]);
            }

            // ---- deferred folds, both tiles ----
            {
                const float d0 = pA0 + qA0, d1 = pA1 + qA1;
                const float d2 = pA2 + qA2, d3 = pA3 + qA3;
                float s;
                s = __fmaf_rn(-(1.0f / 512.0f), d0, __fadd_rn(zzA0, e0));
                if (s < bdA0) { bdA0 = s; biA0 = k0; }
                s = __fmaf_rn(-(1.0f / 512.0f), d1, __fadd_rn(zzA0, e1));
                if (s < bdA1) { bdA1 = s; biA1 = k0 + 1; }
                s = __fmaf_rn(-(1.0f / 512.0f), d2, __fadd_rn(zzA8, e0));
                if (s < bdA2) { bdA2 = s; biA2 = k0; }
                s = __fmaf_rn(-(1.0f / 512.0f), d3, __fadd_rn(zzA8, e1));
                if (s < bdA3) { bdA3 = s; biA3 = k0 + 1; }
            }
            {
                const float d0 = pB0 + qB0, d1 = pB1 + qB1;
                const float d2 = pB2 + qB2, d3 = pB3 + qB3;
                float s;
                s = __fmaf_rn(-(1.0f / 512.0f), d0, __fadd_rn(zzB0, e0));
                if (s < bdB0) { bdB0 = s; biB0 = k0; }
                s = __fmaf_rn(-(1.0f / 512.0f), d1, __fadd_rn(zzB0, e1));
                if (s < bdB1) { bdB1 = s; biB1 = k0 + 1; }
                s = __fmaf_rn(-(1.0f / 512.0f), d2, __fadd_rn(zzB8, e0));
                if (s < bdB2) { bdB2 = s; biB2 = k0; }
                s = __fmaf_rn(-(1.0f / 512.0f), d3, __fadd_rn(zzB8, e1));
                if (s < bdB3) { bdB3 = s; biB3 = k0 + 1; }
            }
        }
        __syncthreads();
    }

    // ---- reduce: in-lane col pair, then quad; per tile ----
    amerge(bdA0, biA0, bdA1, biA1);
    amerge(bdA2, biA2, bdA3, biA3);
    amerge(bdB0, biB0, bdB1, biB1);
    amerge(bdB2, biB2, bdB3, biB3);
#pragma unroll
    for (int x = 1; x <= 2; x <<= 1) {
        float od; int oi;
        od = __shfl_xor_sync(0xffffffff, bdA0, x);
        oi = __shfl_xor_sync(0xffffffff, biA0, x);
        amerge(bdA0, biA0, od, oi);
        od = __shfl_xor_sync(0xffffffff, bdA2, x);
        oi = __shfl_xor_sync(0xffffffff, biA2, x);
        amerge(bdA2, biA2, od, oi);
        od = __shfl_xor_sync(0xffffffff, bdB0, x);
        oi = __shfl_xor_sync(0xffffffff, biB0, x);
        amerge(bdB0, biB0, od, oi);
        od = __shfl_xor_sync(0xffffffff, bdB2, x);
        oi = __shfl_xor_sync(0xffffffff, biB2, x);
        amerge(bdB2, biB2, od, oi);
    }
    if ((lane & 3) == 0) {
        sidx[w * 32 + rq]      = biA0;
        sidx[w * 32 + 8 + rq]  = biA2;
        sidx[w * 32 + 16 + rq] = biB0;
        sidx[w * 32 + 24 + rq] = biB2;
    }
    __syncthreads();

    // ---- epilogue: gather, straight-through (bit-exact), loss; px = t ----
    float* ob = out + ((size_t)b << 18) + po;
    const float4* er4 = (const float4*)(embed + sidx[t] * CDIM);
    float lp = 0.0f;
#pragma unroll
    for (int j = 0; j < 16; ++j) {
        float4 qv = er4[j];
        int c = j * 4;
        float z0 = zb[((c + 0) << 12) + t];
        float z1 = zb[((c + 1) << 12) + t];
        float z2 = zb[((c + 2) << 12) + t];
        float z3 = zb[((c + 3) << 12) + t];
        float d0 = __fadd_rn(qv.x, -z0);
        float d1 = __fadd_rn(qv.y, -z1);
        float d2 = __fadd_rn(qv.z, -z2);
        float d3 = __fadd_rn(qv.w, -z3);
        ob[((c + 0) << 12) + t] = __fadd_rn(z0, d0);
        ob[((c + 1) << 12) + t] = __fadd_rn(z1, d1);
        ob[((c + 2) << 12) + t] = __fadd_rn(z2, d2);
        ob[((c + 3) << 12) + t] = __fadd_rn(z3, d3);
        lp += d0 * d0 + d1 * d1 + d2 * d2 + d3 * d3;
    }
    // warp-shuffle loss reduction, then 1 barrier + warp0 combine
#pragma unroll
    for (int x = 16; x > 0; x >>= 1)
        lp += __shfl_xor_sync(0xffffffff, lp, x);
    if (lane == 0) red[w] = lp;
    __syncthreads();
    if (t == 0 && out_size > OUT_Q) {
        float s = red[0] + red[1] + red[2] + red[3]
                + red[4] + red[5] + red[6] + red[7];
        atomicAdd(&out[OUT_Q], s * (1.25f / (float)OUT_Q));
    }
}

extern "C" void kernel_launch(void* const* d_in, const int* in_sizes, int n_in,
                              void* d_out, int out_size) {
    const float* z     = (const float*)d_in[0];
    const float* embed = (const float*)d_in[1];
    float* out = (float*)d_out;

    static int configured = 0;
    if (!configured) {
        cudaFuncSetAttribute(vq_main, cudaFuncAttributeMaxDynamicSharedMemorySize,
                             SM_TOT);
        configured = 1;
    }

    vq_pre<<<128, 256>>>(embed, out, out_size);
    vq_main<<<NPX / MPX, TPB, SM_TOT>>>(z, embed, out, out_size);
}

// round 17
// speedup vs baseline: 1.4847x; 1.4847x over previous
#include <cuda_runtime.h>
#include <cuda_fp16.h>
#include <cstdint>

// VectorQuantizer via mma.sync (HMMA) fp16 3-product split-GEMM.
// Warp owns 32 pixel rows (2 m16 tiles) sharing one B load.
// R14 hot loop verbatim; bottom chunk barrier removed; shuffle loss epilogue.
// z [16,64,64,64] f32, embed [1024,64] f32.
// out[0..4194303] = z_q_st, out[4194304] = loss.

#define CDIM   64
#define NPX    65536
#define OUT_Q  4194304
#define KTOT   1024
#define TPB    256
#define MPX    256         // pixels per CTA
#define CHK    32          // codes per chunk (double-buffered)
#define NCHUNK 32
#define NGRP   4           // 8-code groups per chunk
#define ROWB   144         // padded row bytes -> conflict-free ldmatrix

// ---- smem byte offsets ----
#define SM_ZH   0                         // [256 px][72 halves] 36864
#define SM_ZL   36864
#define SM_EB   73728                     // 2 bufs x {EH 4608, EL 4608} = 18432
#define SM_EE   92160                     // [1024] f32
#define SM_ZZ   96256                     // [256] f32
#define SM_IDX  97280                     // [256] int
#define SM_RED  98304                     // [8] f32 warp partials
#define SM_TOT  99328
#define EBUF(b) (SM_EB + (b) * 9216)

__device__ uint4 g_ebh[KTOT * 8];   // fp16(1024*e)  [1024][64] halves
__device__ uint4 g_ebl[KTOT * 8];   // fp16 residual
__device__ float g_ee[KTOT];

__device__ __forceinline__ uint32_t smem_u32(const void* p) {
    uint32_t a;
    asm("{ .reg .u64 t; cvta.to.shared.u64 t, %1; cvt.u32.u64 %0, t; }"
        : "=r"(a) : "l"(p));
    return a;
}
__device__ __forceinline__ void ldsm4(uint32_t& r0, uint32_t& r1, uint32_t& r2,
                                      uint32_t& r3, uint32_t addr) {
    asm volatile("ldmatrix.sync.aligned.m8n8.x4.shared.b16 {%0,%1,%2,%3}, [%4];"
                 : "=r"(r0), "=r"(r1), "=r"(r2), "=r"(r3) : "r"(addr));
}
__device__ __forceinline__ void mma16816(float& d0, float& d1, float& d2, float& d3,
                                         uint32_t a0, uint32_t a1, uint32_t a2,
                                         uint32_t a3, uint32_t b0, uint32_t b1) {
    asm volatile(
        "mma.sync.aligned.m16n8k16.row.col.f32.f16.f16.f32 "
        "{%0,%1,%2,%3}, {%4,%5,%6,%7}, {%8,%9}, {%0,%1,%2,%3};"
        : "+f"(d0), "+f"(d1), "+f"(d2), "+f"(d3)
        : "r"(a0), "r"(a1), "r"(a2), "r"(a3), "r"(b0), "r"(b1));
}
__device__ __forceinline__ void amerge(float& d, int& i, float d2, int i2) {
    if (d2 < d || (d2 == d && i2 < i)) { d = d2; i = i2; }
}
#define CPA16(s, g) \
    asm volatile("cp.async.cg.shared.global [%0], [%1], 16;" \
                 :: "r"(s), "l"(g) : "memory")
#define CPA_COMMIT() asm volatile("cp.async.commit_group;" ::: "memory")
#define CPA_WAIT0()  asm volatile("cp.async.wait_group 0;" ::: "memory")

// ---------------- precompute: split codebook, ee (warp per code) ----------------
__global__ void vq_pre(const float* __restrict__ embed, float* out, int out_size) {
    const int gid  = blockIdx.x * blockDim.x + threadIdx.x;
    const int k    = gid >> 5;            // warp id = code
    const int lane = threadIdx.x & 31;
    if (gid == 0 && out_size > OUT_Q) out[OUT_Q] = 0.0f;
    if (k >= KTOT) return;

    float2 v = *(const float2*)(embed + k * CDIM + lane * 2);   // coalesced
    float s = v.x * v.x + v.y * v.y;
#pragma unroll
    for (int x = 16; x > 0; x >>= 1)
        s += __shfl_xor_sync(0xffffffff, s, x);                 // ee (order-free)

    float w0 = v.x * 1024.0f, w1 = v.y * 1024.0f;               // exact scaling
    __half h0 = __float2half_rn(w0);
    __half h1 = __float2half_rn(w1);
    __half l0 = __float2half_rn(w0 - __half2float(h0));
    __half l1 = __float2half_rn(w1 - __half2float(h1));
    ((__half2*)g_ebh)[k * 32 + lane] = __halves2half2(h0, h1);  // coalesced
    ((__half2*)g_ebl)[k * 32 + lane] = __halves2half2(l0, l1);
    if (lane == 0) g_ee[k] = s;
}

// ---------------- main kernel ----------------
__global__ __launch_bounds__(TPB, 2)
void vq_main(const float* __restrict__ z,
             const float* __restrict__ embed,
             float* __restrict__ out, int out_size)
{
    extern __shared__ unsigned char smem[];
    const uint32_t sb = smem_u32(smem);
    float* ee  = (float*)(smem + SM_EE);
    float* szz = (float*)(smem + SM_ZZ);
    int*   sidx = (int*)(smem + SM_IDX);
    float* red = (float*)(smem + SM_RED);

    const int t    = threadIdx.x;
    const int lane = t & 31;
    const int w    = t >> 5;              // warp 0..7: rows w*32..w*32+31

    const int base = blockIdx.x * MPX;
    const int b    = base >> 12;
    const int po   = base & 4095;
    const float* zb = z + ((size_t)b << 18) + po;

    // ---- stage chunk 0 immediately ----
    {
        uint32_t off = (uint32_t)((t >> 3) * ROWB + (t & 7) * 16);
        CPA16(sb + EBUF(0) + off,        g_ebh + t);
        CPA16(sb + EBUF(0) + 4608 + off, g_ebl + t);
        CPA_COMMIT();
    }

    // ---- ee table ----
#pragma unroll
    for (int j = 0; j < 4; ++j) ee[t + j * 256] = g_ee[t + j * 256];

    // ---- load z column for my pixel (px = t): split + zz in one pass ----
    {
        __half* zhp = (__half*)(smem + SM_ZH) + t * 72;
        __half* zlp = (__half*)(smem + SM_ZL) + t * 72;
        float s = 0.0f;
#pragma unroll
        for (int c = 0; c < CDIM; ++c) {
            float v = zb[(c << 12) + t];
            s = __fadd_rn(s, __fmul_rn(v, v));    // reference rounding, sequential
            __half h = __float2half_rn(v);
            __half l = __float2half_rn(v - __half2float(h));
            zhp[c] = h;
            zlp[c] = l;
        }
        szz[t] = s;
    }
    __syncthreads();

    // ---- A fragments (register resident): 2 tiles x 4 ksteps x {zh, zl} ----
    uint32_t aH[2][4][4], aL[2][4][4];
    {
        const int m    = lane >> 3;
        const int coff = (m >> 1) * 16;
#pragma unroll
        for (int tl = 0; tl < 2; ++tl) {
            const int arow = w * 32 + tl * 16 + (m & 1) * 8 + (lane & 7);
            uint32_t adH = sb + SM_ZH + arow * ROWB + coff;
            uint32_t adL = sb + SM_ZL + arow * ROWB + coff;
#pragma unroll
            for (int ks = 0; ks < 4; ++ks) {
                ldsm4(aH[tl][ks][0], aH[tl][ks][1], aH[tl][ks][2], aH[tl][ks][3],
                      adH + ks * 32);
                ldsm4(aL[tl][ks][0], aL[tl][ks][1], aL[tl][ks][2], aL[tl][ks][3],
                      adL + ks * 32);
            }
        }
    }

    const int rq = lane >> 2;
    const float zzA0 = szz[w * 32 + rq],      zzA8 = szz[w * 32 + 8 + rq];
    const float zzB0 = szz[w * 32 + 16 + rq], zzB8 = szz[w * 32 + 24 + rq];

    float bdA0 = 3.4e38f, bdA1 = 3.4e38f, bdA2 = 3.4e38f, bdA3 = 3.4e38f;
    float bdB0 = 3.4e38f, bdB1 = 3.4e38f, bdB2 = 3.4e38f, bdB3 = 3.4e38f;
    int biA0 = 0, biA1 = 0, biA2 = 0, biA3 = 0;
    int biB0 = 0, biB1 = 0, biB2 = 0, biB3 = 0;

    const uint32_t blane = (lane & 7) * ROWB + (lane >> 3) * 16;
    const int cql = 2 * (lane & 3);

    for (int ch = 0; ch < NCHUNK; ++ch) {
        const int buf = ch & 1;
        CPA_WAIT0();
        __syncthreads();   // publishes this chunk + retires all prev-chunk reads

        // prefetch chunk ch+1 into the other buffer
        if (ch + 1 < NCHUNK) {
            const uint4* srcH = g_ebh + (ch + 1) * CHK * 8;
            const uint4* srcL = g_ebl + (ch + 1) * CHK * 8;
            const uint32_t db = sb + EBUF(buf ^ 1);
            uint32_t off = (uint32_t)((t >> 3) * ROWB + (t & 7) * 16);
            CPA16(db + off,        srcH + t);
            CPA16(db + 4608 + off, srcL + t);
            CPA_COMMIT();
        }

        const uint32_t bH0 = sb + EBUF(buf) + blane;
        const uint32_t bL0 = bH0 + 4608;

#pragma unroll
        for (int g = 0; g < NGRP; ++g) {
            const uint32_t bo = (uint32_t)(g * 8 * ROWB);
            uint32_t bh[8], bl[8];
            ldsm4(bh[0], bh[1], bh[2], bh[3], bH0 + bo);
            ldsm4(bh[4], bh[5], bh[6], bh[7], bH0 + bo + 64);
            ldsm4(bl[0], bl[1], bl[2], bl[3], bL0 + bo);
            ldsm4(bl[4], bl[5], bl[6], bl[7], bL0 + bo + 64);

            const int k0 = ch * CHK + g * 8 + cql;
            const float e0 = ee[k0], e1 = ee[k0 + 1];

            // ---- tile 0: 12 MMAs, 3 independent chains ----
            {
                float p0 = 0.f, p1 = 0.f, p2 = 0.f, p3 = 0.f;
                float q0 = 0.f, q1 = 0.f, q2 = 0.f, q3 = 0.f;
                float r0 = 0.f, r1 = 0.f, r2 = 0.f, r3 = 0.f;
#pragma unroll
                for (int ks = 0; ks < 4; ++ks) {
                    mma16816(p0, p1, p2, p3, aH[0][ks][0], aH[0][ks][1],
                             aH[0][ks][2], aH[0][ks][3], bh[2 * ks], bh[2 * ks + 1]);
                    mma16816(q0, q1, q2, q3, aH[0][ks][0], aH[0][ks][1],
                             aH[0][ks][2], aH[0][ks][3], bl[2 * ks], bl[2 * ks + 1]);
                    mma16816(r0, r1, r2, r3, aL[0][ks][0], aL[0][ks][1],
                             aL[0][ks][2], aL[0][ks][3], bh[2 * ks], bh[2 * ks + 1]);
                }
                const float d0 = (p0 + q0) + r0, d1 = (p1 + q1) + r1;
                const float d2 = (p2 + q2) + r2, d3 = (p3 + q3) + r3;
                float s;
                s = __fmaf_rn(-(1.0f / 512.0f), d0, __fadd_rn(zzA0, e0));
                if (s < bdA0) { bdA0 = s; biA0 = k0; }
                s = __fmaf_rn(-(1.0f / 512.0f), d1, __fadd_rn(zzA0, e1));
                if (s < bdA1) { bdA1 = s; biA1 = k0 + 1; }
                s = __fmaf_rn(-(1.0f / 512.0f), d2, __fadd_rn(zzA8, e0));
                if (s < bdA2) { bdA2 = s; biA2 = k0; }
                s = __fmaf_rn(-(1.0f / 512.0f), d3, __fadd_rn(zzA8, e1));
                if (s < bdA3) { bdA3 = s; biA3 = k0 + 1; }
            }
            // ---- tile 1 ----
            {
                float p0 = 0.f, p1 = 0.f, p2 = 0.f, p3 = 0.f;
                float q0 = 0.f, q1 = 0.f, q2 = 0.f, q3 = 0.f;
                float r0 = 0.f, r1 = 0.f, r2 = 0.f, r3 = 0.f;
#pragma unroll
                for (int ks = 0; ks < 4; ++ks) {
                    mma16816(p0, p1, p2, p3, aH[1][ks][0], aH[1][ks][1],
                             aH[1][ks][2], aH[1][ks][3], bh[2 * ks], bh[2 * ks + 1]);
                    mma16816(q0, q1, q2, q3, aH[1][ks][0], aH[1][ks][1],
                             aH[1][ks][2], aH[1][ks][3], bl[2 * ks], bl[2 * ks + 1]);
                    mma16816(r0, r1, r2, r3, aL[1][ks][0], aL[1][ks][1],
                             aL[1][ks][2], aL[1][ks][3], bh[2 * ks], bh[2 * ks + 1]);
                }
                const float d0 = (p0 + q0) + r0, d1 = (p1 + q1) + r1;
                const float d2 = (p2 + q2) + r2, d3 = (p3 + q3) + r3;
                float s;
                s = __fmaf_rn(-(1.0f / 512.0f), d0, __fadd_rn(zzB0, e0));
                if (s < bdB0) { bdB0 = s; biB0 = k0; }
                s = __fmaf_rn(-(1.0f / 512.0f), d1, __fadd_rn(zzB0, e1));
                if (s < bdB1) { bdB1 = s; biB1 = k0 + 1; }
                s = __fmaf_rn(-(1.0f / 512.0f), d2, __fadd_rn(zzB8, e0));
                if (s < bdB2) { bdB2 = s; biB2 = k0; }
                s = __fmaf_rn(-(1.0f / 512.0f), d3, __fadd_rn(zzB8, e1));
                if (s < bdB3) { bdB3 = s; biB3 = k0 + 1; }
            }
        }
        // no bottom barrier: next chunk's top barrier orders all reads of this
        // buffer before the following prefetch can overwrite it.
    }

    // ---- reduce: in-lane col pair, then quad; per tile ----
    amerge(bdA0, biA0, bdA1, biA1);
    amerge(bdA2, biA2, bdA3, biA3);
    amerge(bdB0, biB0, bdB1, biB1);
    amerge(bdB2, biB2, bdB3, biB3);
#pragma unroll
    for (int x = 1; x <= 2; x <<= 1) {
        float od; int oi;
        od = __shfl_xor_sync(0xffffffff, bdA0, x);
        oi = __shfl_xor_sync(0xffffffff, biA0, x);
        amerge(bdA0, biA0, od, oi);
        od = __shfl_xor_sync(0xffffffff, bdA2, x);
        oi = __shfl_xor_sync(0xffffffff, biA2, x);
        amerge(bdA2, biA2, od, oi);
        od = __shfl_xor_sync(0xffffffff, bdB0, x);
        oi = __shfl_xor_sync(0xffffffff, biB0, x);
        amerge(bdB0, biB0, od, oi);
        od = __shfl_xor_sync(0xffffffff, bdB2, x);
        oi = __shfl_xor_sync(0xffffffff, biB2, x);
        amerge(bdB2, biB2, od, oi);
    }
    if ((lane & 3) == 0) {
        sidx[w * 32 + rq]      = biA0;
        sidx[w * 32 + 8 + rq]  = biA2;
        sidx[w * 32 + 16 + rq] = biB0;
        sidx[w * 32 + 24 + rq] = biB2;
    }
    __syncthreads();

    // ---- epilogue: gather, straight-through (bit-exact), loss; px = t ----
    float* ob = out + ((size_t)b << 18) + po;
    const float4* er4 = (const float4*)(embed + sidx[t] * CDIM);
    float lp = 0.0f;
#pragma unroll
    for (int j = 0; j < 16; ++j) {
        float4 qv = er4[j];
        int c = j * 4;
        float z0 = zb[((c + 0) << 12) + t];
        float z1 = zb[((c + 1) << 12) + t];
        float z2 = zb[((c + 2) << 12) + t];
        float z3 = zb[((c + 3) << 12) + t];
        float d0 = __fadd_rn(qv.x, -z0);
        float d1 = __fadd_rn(qv.y, -z1);
        float d2 = __fadd_rn(qv.z, -z2);
        float d3 = __fadd_rn(qv.w, -z3);
        ob[((c + 0) << 12) + t] = __fadd_rn(z0, d0);
        ob[((c + 1) << 12) + t] = __fadd_rn(z1, d1);
        ob[((c + 2) << 12) + t] = __fadd_rn(z2, d2);
        ob[((c + 3) << 12) + t] = __fadd_rn(z3, d3);
        lp += d0 * d0 + d1 * d1 + d2 * d2 + d3 * d3;
    }
    // warp-shuffle loss reduction, then 1 barrier + thread0 combine
#pragma unroll
    for (int x = 16; x > 0; x >>= 1)
        lp += __shfl_xor_sync(0xffffffff, lp, x);
    if (lane == 0) red[w] = lp;
    __syncthreads();
    if (t == 0 && out_size > OUT_Q) {
        float s = red[0] + red[1] + red[2] + red[3]
                + red[4] + red[5] + red[6] + red[7];
        atomicAdd(&out[OUT_Q], s * (1.25f / (float)OUT_Q));
    }
}

extern "C" void kernel_launch(void* const* d_in, const int* in_sizes, int n_in,
                              void* d_out, int out_size) {
    const float* z     = (const float*)d_in[0];
    const float* embed = (const float*)d_in[1];
    float* out = (float*)d_out;

    static int configured = 0;
    if (!configured) {
        cudaFuncSetAttribute(vq_main, cudaFuncAttributeMaxDynamicSharedMemorySize,
                             SM_TOT);
        configured = 1;
    }

    vq_pre<<<128, 256>>>(embed, out, out_size);
    vq_main<<<NPX / MPX, TPB, SM_TOT>>>(z, embed, out, out_size);
}